// round 4
// baseline (speedup 1.0000x reference)
#include <cuda_runtime.h>
#include <stdint.h>

// reference(x) = (U*S)@Vh from SVD of x == exact SVD reconstruction == x.
// Kernel = pure D2D copy of N*3*3 floats. We're at ~86% of HBM R+W spec with
// a hand-rolled SM copy; test the driver's tuned D2D path (256-bit accesses,
// driver-shaped grid) via a graph-capturable cudaMemcpyAsync node.

#define CP_THREADS 256
#define CP_UNROLL  8

// Fallback SM copy (only used if memcpy can't be issued) — R2 version.
__global__ void __launch_bounds__(CP_THREADS) copy_unroll_kernel(
    const float4* __restrict__ src, float4* __restrict__ dst, long long n4)
{
    long long base = (long long)blockIdx.x * (CP_THREADS * CP_UNROLL) + threadIdx.x;
    if (base + (long long)(CP_UNROLL - 1) * CP_THREADS < n4) {
        float4 v[CP_UNROLL];
#pragma unroll
        for (int u = 0; u < CP_UNROLL; u++)
            v[u] = src[base + (long long)u * CP_THREADS];
#pragma unroll
        for (int u = 0; u < CP_UNROLL; u++)
            dst[base + (long long)u * CP_THREADS] = v[u];
    } else {
#pragma unroll
        for (int u = 0; u < CP_UNROLL; u++) {
            long long i = base + (long long)u * CP_THREADS;
            if (i < n4) dst[i] = src[i];
        }
    }
}

extern "C" void kernel_launch(void* const* d_in, const int* in_sizes, int n_in,
                              void* d_out, int out_size) {
    const float* x = (const float*)d_in[0];
    float* out = (float*)d_out;
    long long n = (long long)in_sizes[0];   // total float elements (N*3*3)

    cudaError_t st = cudaMemcpyAsync(out, x, (size_t)n * sizeof(float),
                                     cudaMemcpyDeviceToDevice, 0);
    if (st != cudaSuccess) {
        // fallback: hand-rolled SM copy
        long long n4 = n / 4;
        long long per_block = (long long)CP_THREADS * CP_UNROLL;
        int blocks = (int)((n4 + per_block - 1) / per_block);
        if (blocks > 0)
            copy_unroll_kernel<<<blocks, CP_THREADS>>>((const float4*)x, (float4*)out, n4);
    }
}